// round 14
// baseline (speedup 1.0000x reference)
#include <cuda_runtime.h>
#include <cuda_fp16.h>
#include <cstdint>

#define V 50000
#define VPAD 53248            // V rounded up to 4096-multiple for int4 scan
#define BDIM 4
#define CIN 128
#define COUT 128
#define KCHEB 4
#define FDIM 512              // B*Cin
#define EMAX 800000

// ---------------- scratch (device globals; allocation-free rule) -------------
__device__ __half g_x[KCHEB][(size_t)V * FDIM];

__device__ __align__(16) int g_hist[VPAD];   // zero at load; re-zeroed in prep2
__device__ int   g_rowptr[V + 1];
__device__ int   g_cursor[V];
__device__ int   g_col[EMAX];
__device__ float g_val[EMAX];

// W pre-packed in GEMM fragment layout, single fp16:
// [kb*4+j][ (nt*32+lane)*4 + (ks*2+slotB) ]  (uint32 = half2)
__device__ uint32_t g_wfrag[KCHEB * 4][2048];

// ---------------- helpers ------------------------------------------------------
__device__ __forceinline__ uint32_t smem_u32(const void* p) {
    uint32_t a;
    asm("{ .reg .u64 t; cvta.to.shared.u64 t, %1; cvt.u32.u64 %0, t; }" : "=r"(a) : "l"(p));
    return a;
}
__device__ __forceinline__ void mma_f16(float& c0, float& c1, float& c2, float& c3,
                                        uint32_t a0, uint32_t a1, uint32_t a2, uint32_t a3,
                                        uint32_t b0, uint32_t b1) {
    asm volatile(
        "mma.sync.aligned.m16n8k16.row.col.f32.f16.f16.f32 "
        "{%0,%1,%2,%3}, {%4,%5,%6,%7}, {%8,%9}, {%0,%1,%2,%3};"
        : "+f"(c0), "+f"(c1), "+f"(c2), "+f"(c3)
        : "r"(a0), "r"(a1), "r"(a2), "r"(a3), "r"(b0), "r"(b1));
}
__device__ __forceinline__ void cp_async16(void* sdst, const void* gsrc) {
    uint32_t sa = smem_u32(sdst);
    asm volatile("cp.async.cg.shared.global [%0], [%1], 16;" :: "r"(sa), "l"(gsrc) : "memory");
}
#define CP_COMMIT() asm volatile("cp.async.commit_group;" ::: "memory")
#define CP_WAIT0()  asm volatile("cp.async.wait_group 0;" ::: "memory")

// ---------------- prep1: transpose (x -> g_x[0] fp16) || edge histogram -------
#define TB_X 1563                 // ceil(V/32)
#define TB_Y 8                    // FDIM/64
#define TB_TOTAL (TB_X * TB_Y)
__global__ void prep1_kernel(const float* __restrict__ x,
                             const int* __restrict__ row, int E) {
    __shared__ float tile[64][33];
    int bid = blockIdx.x;
    int t   = threadIdx.x;
    if (bid < TB_TOTAL) {
        int bx = bid % TB_X;
        int by = bid / TB_X;
        int v0 = bx * 32;
        int f0 = by * 64;
        int tx = t & 31;
        int ty = t >> 5;                 // 0..7
        #pragma unroll
        for (int r = 0; r < 8; r++) {
            int fl = ty * 8 + r;         // 0..63
            int v  = v0 + tx;
            tile[fl][tx] = (v < V) ? x[(size_t)(f0 + fl) * V + v] : 0.f;
        }
        __syncthreads();
        int vq = t >> 3;                 // 0..31
        int fq = t & 7;                  // 0..7
        int v  = v0 + vq;
        if (v < V) {
            __half hbuf[8];
            #pragma unroll
            for (int j = 0; j < 8; j++)
                hbuf[j] = __float2half_rn(tile[fq * 8 + j][vq]);
            *(uint4*)(&g_x[0][(size_t)v * FDIM + f0 + fq * 8]) = *(uint4*)hbuf;
        }
    } else {
        int i = (bid - TB_TOTAL) * blockDim.x + t;
        if (i < E) atomicAdd(&g_hist[row[i]], 1);
    }
}

// ---------------- scan: 4 elems/thread, 13 iterations ---------------------------
__global__ void scan_kernel() {
    __shared__ int wsum[32];
    __shared__ int s_carry;
    int tid  = threadIdx.x;
    int lane = tid & 31;
    int w    = tid >> 5;
    if (tid == 0) { s_carry = 0; g_rowptr[0] = 0; }
    __syncthreads();
    for (int base = 0; base < V; base += 4096) {
        int i0 = base + tid * 4;
        int4 h4 = *(const int4*)&g_hist[i0];
        int h[4] = { h4.x, h4.y, h4.z, h4.w };
        int tsum = h[0] + h[1] + h[2] + h[3];
        int s = tsum;
        #pragma unroll
        for (int off = 1; off < 32; off <<= 1) {
            int n = __shfl_up_sync(0xFFFFFFFFu, s, off);
            if (lane >= off) s += n;
        }
        if (lane == 31) wsum[w] = s;
        __syncthreads();
        if (w == 0) {
            int t2 = wsum[lane];
            #pragma unroll
            for (int off = 1; off < 32; off <<= 1) {
                int n = __shfl_up_sync(0xFFFFFFFFu, t2, off);
                if (lane >= off) t2 += n;
            }
            wsum[lane] = t2;
        }
        __syncthreads();
        int c    = s_carry;
        int excl = s - tsum + ((w > 0) ? wsum[w - 1] : 0) + c;
        int run  = excl;
        #pragma unroll
        for (int j = 0; j < 4; j++) {
            int idx = i0 + j;
            if (idx < V) {
                g_cursor[idx] = run;
                run += h[j];
                g_rowptr[idx + 1] = run;
            }
        }
        int total = wsum[31];
        __syncthreads();
        if (tid == 0) s_carry = c + total;
        __syncthreads();
    }
}

// ---------------- prep2: scatter || wprep || hist re-zero -----------------------
// hist is consumed by scan (previous kernel); zero it here so the next graph
// replay starts from a clean histogram (module load starts zeroed too).
__global__ void prep2_kernel(const int* __restrict__ row,
                             const int* __restrict__ col,
                             const float* __restrict__ val, int E,
                             const float* __restrict__ W, int scatBlocks,
                             int wprepBlocks) {
    int bid = blockIdx.x;
    int t   = threadIdx.x;
    if (bid < scatBlocks) {
        int i = bid * blockDim.x + t;
        if (i < E) {
            int r = row[i];
            int p = atomicAdd(&g_cursor[r], 1);
            g_col[p] = col[i];
            g_val[p] = val[i];
        }
    } else if (bid < scatBlocks + wprepBlocks) {
        int idx = (bid - scatBlocks) * blockDim.x + t;  // kb x o x c2
        if (idx >= KCHEB * COUT * 64) return;
        int c2 = idx & 63;
        int o  = (idx >> 6) & 127;
        int kb = idx >> 13;
        int c  = c2 * 2;
        float w0 = W[((size_t)(kb * CIN + c))     * COUT + o];
        float w1 = W[((size_t)(kb * CIN + c + 1)) * COUT + o];
        __half2 H = __floats2half2_rn(w0, w1);
        uint32_t hi = *reinterpret_cast<uint32_t*>(&H);
        int j     = c2 >> 4;
        int cr    = c & 31;
        int ks    = cr >> 4;
        int kk    = cr & 15;
        int p     = kk >> 1;
        int gc    = p & 3;
        int slotB = p >> 2;
        int nt    = o >> 3;
        int gn    = o & 7;
        int lane  = gn * 4 + gc;
        g_wfrag[kb * 4 + j][(nt * 32 + lane) * 4 + ks * 2 + slotB] = hi;
    } else {
        // zero hist for the next replay (scan already consumed it)
        int i = (bid - scatBlocks - wprepBlocks) * blockDim.x + t;
        if (i * 4 < VPAD) *(int4*)&g_hist[i * 4] = make_int4(0, 0, 0, 0);
    }
}

// ---------------- SpMM + Chebyshev combine: one warp per FULL row ---------------
__global__ void spmm_cheb_kernel(int ii, int pi, int oi,
                                 float alpha, float beta) {
    const __half* __restrict__ xin   = &g_x[ii][0];
    const __half* __restrict__ xprev = &g_x[pi][0];
    __half*       __restrict__ xout  = &g_x[oi][0];

    int r    = blockIdx.x * (blockDim.x >> 5) + (threadIdx.x >> 5);
    int lane = threadIdx.x & 31;
    if (r >= V) return;
    int o1 = lane * 8;          // halves [o1, o1+8)
    int o2 = 256 + lane * 8;    // halves [o2, o2+8)

    int e0 = g_rowptr[r];
    int e1 = g_rowptr[r + 1];

    float s[16];
    #pragma unroll
    for (int i = 0; i < 16; i++) s[i] = 0.f;

    auto accq = [&](uint4 ra, float wv, int base) {
        float2 a0 = __half22float2(*reinterpret_cast<__half2*>(&ra.x));
        float2 a1 = __half22float2(*reinterpret_cast<__half2*>(&ra.y));
        float2 a2 = __half22float2(*reinterpret_cast<__half2*>(&ra.z));
        float2 a3 = __half22float2(*reinterpret_cast<__half2*>(&ra.w));
        s[base + 0] += wv * a0.x;  s[base + 1] += wv * a0.y;
        s[base + 2] += wv * a1.x;  s[base + 3] += wv * a1.y;
        s[base + 4] += wv * a2.x;  s[base + 5] += wv * a2.y;
        s[base + 6] += wv * a3.x;  s[base + 7] += wv * a3.y;
    };

    int e = e0;
    for (; e + 1 < e1; e += 2) {
        int   c0 = __ldg(&g_col[e]);
        int   c1 = __ldg(&g_col[e + 1]);
        float w0 = __ldg(&g_val[e]);
        float w1 = __ldg(&g_val[e + 1]);
        const __half* p0 = xin + (size_t)c0 * FDIM;
        const __half* p1 = xin + (size_t)c1 * FDIM;
        uint4 a0 = __ldg((const uint4*)(p0 + o1));
        uint4 a1 = __ldg((const uint4*)(p0 + o2));
        uint4 b0 = __ldg((const uint4*)(p1 + o1));
        uint4 b1 = __ldg((const uint4*)(p1 + o2));
        accq(a0, w0, 0);  accq(a1, w0, 8);
        accq(b0, w1, 0);  accq(b1, w1, 8);
    }
    if (e < e1) {
        int   c0 = __ldg(&g_col[e]);
        float w0 = __ldg(&g_val[e]);
        const __half* p0 = xin + (size_t)c0 * FDIM;
        uint4 a0 = __ldg((const uint4*)(p0 + o1));
        uint4 a1 = __ldg((const uint4*)(p0 + o2));
        accq(a0, w0, 0);  accq(a1, w0, 8);
    }

    if (beta != 0.f) {
        const __half* pp = xprev + (size_t)r * FDIM;
        uint4 pr0 = __ldcs((const uint4*)(pp + o1));
        uint4 pr1 = __ldcs((const uint4*)(pp + o2));
        uint32_t pu[8] = { pr0.x, pr0.y, pr0.z, pr0.w, pr1.x, pr1.y, pr1.z, pr1.w };
        #pragma unroll
        for (int q = 0; q < 8; q++) {
            float2 p2 = __half22float2(*reinterpret_cast<__half2*>(&pu[q]));
            s[q * 2 + 0] = alpha * s[q * 2 + 0] + beta * p2.x;
            s[q * 2 + 1] = alpha * s[q * 2 + 1] + beta * p2.y;
        }
    } else {
        #pragma unroll
        for (int i = 0; i < 16; i++) s[i] *= alpha;
    }

    uint32_t ou[8];
    #pragma unroll
    for (int q = 0; q < 8; q++) {
        __half2 h2 = __floats2half2_rn(s[q * 2], s[q * 2 + 1]);
        ou[q] = *reinterpret_cast<uint32_t*>(&h2);
    }
    __half* po = xout + (size_t)r * FDIM;
    __stcs((uint4*)(po + o1), make_uint4(ou[0], ou[1], ou[2], ou[3]));
    __stcs((uint4*)(po + o2), make_uint4(ou[4], ou[5], ou[6], ou[7]));
}

// ---------------- fp16 mma.sync GEMM (single W) --------------------------------
// Smem (dynamic, 32KB): A[2][512] uint4 (8KB each), B[2][512] uint4 (8KB each)
__global__ void __launch_bounds__(256, 2)
cheb_gemm_mma(const float* __restrict__ bias, float* __restrict__ out) {
    extern __shared__ uint4 sm4[];
    uint4* ASb = sm4;           // [2][512]
    uint4* BSb = sm4 + 1024;    // [2][512]

    int t     = threadIdx.x;
    int wid   = t >> 5;
    int lane  = t & 31;
    int mw    = wid & 3;
    int nw    = wid >> 2;
    int vbase = blockIdx.x * 128;
    int b     = blockIdx.y;

    float acc[2][8][4];
    #pragma unroll
    for (int i = 0; i < 2; i++)
        #pragma unroll
        for (int j = 0; j < 8; j++)
            #pragma unroll
            for (int q = 0; q < 4; q++) acc[i][j][q] = 0.f;

    // A staging mapping: thread (srow, par=ks)
    int par   = t & 1;
    int srow  = t >> 1;
    int smt   = srow >> 4;
    int rr    = srow & 15;
    int sg    = rr & 7;
    int shalf = rr >> 3;
    int v     = vbase + srow;
    bool vok  = (v < V);

    auto ldg_A = [&](uint4* areg, int ca) {
        int kb = ca >> 2;
        int cc = (ca & 3) * 32;
        const __half* arow = &g_x[kb][0] + (size_t)v * FDIM + b * CIN + cc + par * 16;
        if (vok) {
            areg[0] = *(const uint4*)(arow);
            areg[1] = *(const uint4*)(arow + 8);
        } else {
            areg[0] = make_uint4(0, 0, 0, 0);
            areg[1] = make_uint4(0, 0, 0, 0);
        }
    };
    auto sts_A = [&](uint4* areg, int bufi) {
        uint32_t* AS32 = reinterpret_cast<uint32_t*>(ASb + bufi * 512);
        uint32_t q0[4] = { areg[0].x, areg[0].y, areg[0].z, areg[0].w };
        uint32_t q1[4] = { areg[1].x, areg[1].y, areg[1].z, areg[1].w };
        #pragma unroll
        for (int i = 0; i < 4; i++) {
            int lane_i = sg * 4 + i;
            int word = ((smt * 2 + par) * 32 + lane_i) * 4 + 2 * shalf;
            *(uint2*)(AS32 + word) = make_uint2(q0[i], q1[i]);
        }
    };
    auto cp_B = [&](int ca, int bufi) {
        const uint4* src = reinterpret_cast<const uint4*>(g_wfrag[ca]);
        uint4* dst = BSb + bufi * 512;
        #pragma unroll
        for (int s = 0; s < 2; s++)
            cp_async16(dst + t + s * 256, src + t + s * 256);
        CP_COMMIT();
    };

    // ---- prologue
    uint4 areg[2], areg2[2];
    ldg_A(areg, 0);
    cp_B(0, 0);
    sts_A(areg, 0);
    ldg_A(areg2, 1);

    for (int ci = 0; ci < 16; ci++) {
        int cur = ci & 1;
        CP_WAIT0();
        __syncthreads();

        if (ci < 15) {
            cp_B(ci + 1, cur ^ 1);
            sts_A(areg2, cur ^ 1);
            if (ci < 14) ldg_A(areg, ci + 2);
            #pragma unroll
            for (int qi = 0; qi < 2; qi++) { uint4 tmp = areg[qi]; areg[qi] = areg2[qi]; areg2[qi] = tmp; }
        }

        uint4* AS4 = ASb + cur * 512;
        uint4* BS4 = BSb + cur * 512;

        uint4 au[2][2];
        #pragma unroll
        for (int mt2 = 0; mt2 < 2; mt2++) {
            int mt = mw * 2 + mt2;
            au[mt2][0] = AS4[(mt * 2 + 0) * 32 + lane];
            au[mt2][1] = AS4[(mt * 2 + 1) * 32 + lane];
        }
        #pragma unroll
        for (int nt8 = 0; nt8 < 8; nt8++) {
            int nt = nw * 8 + nt8;
            uint4 bu = BS4[nt * 32 + lane];   // {ks0b0, ks0b1, ks1b0, ks1b1}
            #pragma unroll
            for (int mt2 = 0; mt2 < 2; mt2++) {
                float* c = acc[mt2][nt8];
                mma_f16(c[0], c[1], c[2], c[3],
                        au[mt2][0].x, au[mt2][0].z, au[mt2][0].y, au[mt2][0].w,
                        bu.x, bu.y);
                mma_f16(c[0], c[1], c[2], c[3],
                        au[mt2][1].x, au[mt2][1].z, au[mt2][1].y, au[mt2][1].w,
                        bu.z, bu.w);
            }
        }
    }

    // ---- epilogue: streaming stores
    int gid  = lane >> 2;
    int tid4 = lane & 3;
    #pragma unroll
    for (int nt8 = 0; nt8 < 8; nt8++) {
        int o0 = nw * 64 + nt8 * 8 + tid4 * 2;
        float bi0 = __ldg(&bias[o0]);
        float bi1 = __ldg(&bias[o0 + 1]);
        #pragma unroll
        for (int mt2 = 0; mt2 < 2; mt2++) {
            int v0 = vbase + mw * 32 + mt2 * 16 + gid;
            const float* c = acc[mt2][nt8];
            if (v0 < V) {
                __stcs(&out[((size_t)b * COUT + o0)     * V + v0], c[0] + bi0);
                __stcs(&out[((size_t)b * COUT + o0 + 1) * V + v0], c[1] + bi1);
            }
            if (v0 + 8 < V) {
                __stcs(&out[((size_t)b * COUT + o0)     * V + v0 + 8], c[2] + bi0);
                __stcs(&out[((size_t)b * COUT + o0 + 1) * V + v0 + 8], c[3] + bi1);
            }
        }
    }
}

// ---------------- launcher ----------------------------------------------------
extern "C" void kernel_launch(void* const* d_in, const int* in_sizes, int n_in,
                              void* d_out, int out_size) {
    const float* x        = (const float*)d_in[0];
    const int*   edge_row = (const int*)d_in[1];
    const int*   edge_col = (const int*)d_in[2];
    const float* edge_val = (const float*)d_in[3];
    const float* weights  = (const float*)d_in[4];
    const float* biases   = (const float*)d_in[5];
    float*       out      = (float*)d_out;

    int E = in_sizes[1];

    static bool attr_set = false;
    if (!attr_set) {
        cudaFuncSetAttribute(cheb_gemm_mma,
                             cudaFuncAttributeMaxDynamicSharedMemorySize,
                             32768);
        attr_set = true;
    }

    int histBlocks  = (E + 255) / 256;
    int wprepBlocks = (KCHEB * COUT * 64 + 255) / 256;
    int zeroBlocks  = (VPAD / 4 + 255) / 256;

    // prep1: transpose || hist  (hist zeroed at module load / by prior prep2)
    prep1_kernel<<<TB_TOTAL + histBlocks, 256>>>(x, edge_row, E);
    // scan
    scan_kernel<<<1, 1024>>>();
    // prep2: scatter || wprep || hist re-zero
    prep2_kernel<<<histBlocks + wprepBlocks + zeroBlocks, 256>>>(
        edge_row, edge_col, edge_val, E, weights, histBlocks, wprepBlocks);

    // Chebyshev recurrence (one warp per full row)
    {
        dim3 gb((V + 7) / 8);
        spmm_cheb_kernel<<<gb, 256>>>(0, 0, 1, 1.f, 0.f);
        spmm_cheb_kernel<<<gb, 256>>>(1, 0, 2, 2.f, -1.f);
        spmm_cheb_kernel<<<gb, 256>>>(2, 1, 3, 2.f, -1.f);
    }

    // fp16 mma GEMM + bias + output permute
    {
        dim3 gb((V + 127) / 128, BDIM);
        cheb_gemm_mma<<<gb, 256, 32768>>>(biases, out);
    }
}

// round 15
// speedup vs baseline: 1.4847x; 1.4847x over previous
#include <cuda_runtime.h>
#include <cuda_fp16.h>
#include <cstdint>

#define V 50000
#define VPAD 53248            // V rounded up to 4096-multiple for int4 scan
#define BDIM 4
#define CIN 128
#define COUT 128
#define KCHEB 4
#define FDIM 512              // B*Cin
#define EMAX 800000

// ---------------- scratch (device globals; allocation-free rule) -------------
__device__ __half g_x[KCHEB][(size_t)V * FDIM];

__device__ __align__(16) int g_hist[VPAD];
__device__ int   g_rowptr[V + 1];
__device__ int   g_cursor[V];
__device__ int   g_col[EMAX];
__device__ float g_val[EMAX];

// W pre-packed in GEMM fragment layout, single fp16:
// [kb*4+j][ (nt*32+lane)*4 + (ks*2+slotB) ]  (uint32 = half2)
__device__ uint32_t g_wfrag[KCHEB * 4][2048];

// ---------------- helpers ------------------------------------------------------
__device__ __forceinline__ uint32_t smem_u32(const void* p) {
    uint32_t a;
    asm("{ .reg .u64 t; cvta.to.shared.u64 t, %1; cvt.u32.u64 %0, t; }" : "=r"(a) : "l"(p));
    return a;
}
__device__ __forceinline__ void mma_f16(float& c0, float& c1, float& c2, float& c3,
                                        uint32_t a0, uint32_t a1, uint32_t a2, uint32_t a3,
                                        uint32_t b0, uint32_t b1) {
    asm volatile(
        "mma.sync.aligned.m16n8k16.row.col.f32.f16.f16.f32 "
        "{%0,%1,%2,%3}, {%4,%5,%6,%7}, {%8,%9}, {%0,%1,%2,%3};"
        : "+f"(c0), "+f"(c1), "+f"(c2), "+f"(c3)
        : "r"(a0), "r"(a1), "r"(a2), "r"(a3), "r"(b0), "r"(b1));
}
__device__ __forceinline__ void cp_async16(void* sdst, const void* gsrc) {
    uint32_t sa = smem_u32(sdst);
    asm volatile("cp.async.cg.shared.global [%0], [%1], 16;" :: "r"(sa), "l"(gsrc) : "memory");
}
#define CP_COMMIT() asm volatile("cp.async.commit_group;" ::: "memory")
#define CP_WAIT0()  asm volatile("cp.async.wait_group 0;" ::: "memory")

// ---------------- zero hist ----------------------------------------------------
__global__ void zero_hist_kernel() {
    int i = blockIdx.x * blockDim.x + threadIdx.x;
    if (i < VPAD) g_hist[i] = 0;
}

// ---------------- prep1: transpose (x -> g_x[0] fp16) || edge histogram -------
#define TB_X 1563                 // ceil(V/32)
#define TB_Y 8                    // FDIM/64
#define TB_TOTAL (TB_X * TB_Y)
__global__ void prep1_kernel(const float* __restrict__ x,
                             const int* __restrict__ row, int E) {
    __shared__ float tile[64][33];
    int bid = blockIdx.x;
    int t   = threadIdx.x;
    if (bid < TB_TOTAL) {
        int bx = bid % TB_X;
        int by = bid / TB_X;
        int v0 = bx * 32;
        int f0 = by * 64;
        int tx = t & 31;
        int ty = t >> 5;                 // 0..7
        #pragma unroll
        for (int r = 0; r < 8; r++) {
            int fl = ty * 8 + r;         // 0..63
            int v  = v0 + tx;
            tile[fl][tx] = (v < V) ? x[(size_t)(f0 + fl) * V + v] : 0.f;
        }
        __syncthreads();
        int vq = t >> 3;                 // 0..31
        int fq = t & 7;                  // 0..7
        int v  = v0 + vq;
        if (v < V) {
            __half hbuf[8];
            #pragma unroll
            for (int j = 0; j < 8; j++)
                hbuf[j] = __float2half_rn(tile[fq * 8 + j][vq]);
            *(uint4*)(&g_x[0][(size_t)v * FDIM + f0 + fq * 8]) = *(uint4*)hbuf;
        }
    } else {
        int i = (bid - TB_TOTAL) * blockDim.x + t;
        if (i < E) atomicAdd(&g_hist[row[i]], 1);
    }
}

// ---------------- scan: 4 elems/thread, 13 iterations ---------------------------
__global__ void scan_kernel() {
    __shared__ int wsum[32];
    __shared__ int s_carry;
    int tid  = threadIdx.x;
    int lane = tid & 31;
    int w    = tid >> 5;
    if (tid == 0) { s_carry = 0; g_rowptr[0] = 0; }
    __syncthreads();
    for (int base = 0; base < V; base += 4096) {
        int i0 = base + tid * 4;
        int4 h4 = *(const int4*)&g_hist[i0];
        int h[4] = { h4.x, h4.y, h4.z, h4.w };
        int tsum = h[0] + h[1] + h[2] + h[3];
        int s = tsum;
        #pragma unroll
        for (int off = 1; off < 32; off <<= 1) {
            int n = __shfl_up_sync(0xFFFFFFFFu, s, off);
            if (lane >= off) s += n;
        }
        if (lane == 31) wsum[w] = s;
        __syncthreads();
        if (w == 0) {
            int t2 = wsum[lane];
            #pragma unroll
            for (int off = 1; off < 32; off <<= 1) {
                int n = __shfl_up_sync(0xFFFFFFFFu, t2, off);
                if (lane >= off) t2 += n;
            }
            wsum[lane] = t2;
        }
        __syncthreads();
        int c    = s_carry;
        int excl = s - tsum + ((w > 0) ? wsum[w - 1] : 0) + c;
        int run  = excl;
        #pragma unroll
        for (int j = 0; j < 4; j++) {
            int idx = i0 + j;
            if (idx < V) {
                g_cursor[idx] = run;
                run += h[j];
                g_rowptr[idx + 1] = run;
            }
        }
        int total = wsum[31];
        __syncthreads();
        if (tid == 0) s_carry = c + total;
        __syncthreads();
    }
}

// ---------------- prep2: scatter || wprep ---------------------------------------
__global__ void prep2_kernel(const int* __restrict__ row,
                             const int* __restrict__ col,
                             const float* __restrict__ val, int E,
                             const float* __restrict__ W, int scatBlocks) {
    int bid = blockIdx.x;
    if (bid < scatBlocks) {
        int i = bid * blockDim.x + threadIdx.x;
        if (i < E) {
            int r = row[i];
            int p = atomicAdd(&g_cursor[r], 1);
            g_col[p] = col[i];
            g_val[p] = val[i];
        }
    } else {
        int idx = (bid - scatBlocks) * blockDim.x + threadIdx.x;  // kb x o x c2
        if (idx >= KCHEB * COUT * 64) return;
        int c2 = idx & 63;
        int o  = (idx >> 6) & 127;
        int kb = idx >> 13;
        int c  = c2 * 2;
        float w0 = W[((size_t)(kb * CIN + c))     * COUT + o];
        float w1 = W[((size_t)(kb * CIN + c + 1)) * COUT + o];
        __half2 H = __floats2half2_rn(w0, w1);
        uint32_t hi = *reinterpret_cast<uint32_t*>(&H);
        int j     = c2 >> 4;
        int cr    = c & 31;
        int ks    = cr >> 4;
        int kk    = cr & 15;
        int p     = kk >> 1;
        int gc    = p & 3;
        int slotB = p >> 2;
        int nt    = o >> 3;
        int gn    = o & 7;
        int lane  = gn * 4 + gc;
        g_wfrag[kb * 4 + j][(nt * 32 + lane) * 4 + ks * 2 + slotB] = hi;
    }
}

// ---------------- SpMM + Chebyshev combine (16B gathers, 4-edge unroll) --------
__global__ void spmm_cheb_kernel(int ii, int pi, int oi,
                                 float alpha, float beta) {
    const __half* __restrict__ xin   = &g_x[ii][0];
    const __half* __restrict__ xprev = &g_x[pi][0];
    __half*       __restrict__ xout  = &g_x[oi][0];

    int r    = blockIdx.x * (blockDim.x >> 5) + (threadIdx.x >> 5);
    int lane = threadIdx.x & 31;
    if (r >= V) return;
    int fo = (int)blockIdx.y * 256 + (lane << 3);   // half index, 16B aligned

    int e0 = g_rowptr[r];
    int e1 = g_rowptr[r + 1];

    float s0 = 0.f, s1 = 0.f, s2 = 0.f, s3 = 0.f,
          s4 = 0.f, s5 = 0.f, s6 = 0.f, s7 = 0.f;

    auto acc_row = [&](uint4 ra, float wv) {
        float2 a0 = __half22float2(*reinterpret_cast<__half2*>(&ra.x));
        float2 a1 = __half22float2(*reinterpret_cast<__half2*>(&ra.y));
        float2 a2 = __half22float2(*reinterpret_cast<__half2*>(&ra.z));
        float2 a3 = __half22float2(*reinterpret_cast<__half2*>(&ra.w));
        s0 += wv * a0.x;  s1 += wv * a0.y;
        s2 += wv * a1.x;  s3 += wv * a1.y;
        s4 += wv * a2.x;  s5 += wv * a2.y;
        s6 += wv * a3.x;  s7 += wv * a3.y;
    };

    int e = e0;
    for (; e + 3 < e1; e += 4) {
        int   c0 = g_col[e],     c1 = g_col[e + 1];
        int   c2 = g_col[e + 2], c3 = g_col[e + 3];
        float w0 = g_val[e],     w1 = g_val[e + 1];
        float w2 = g_val[e + 2], w3 = g_val[e + 3];
        uint4 ra = __ldg((const uint4*)(xin + (size_t)c0 * FDIM + fo));
        uint4 rb = __ldg((const uint4*)(xin + (size_t)c1 * FDIM + fo));
        uint4 rc = __ldg((const uint4*)(xin + (size_t)c2 * FDIM + fo));
        uint4 rd = __ldg((const uint4*)(xin + (size_t)c3 * FDIM + fo));
        acc_row(ra, w0); acc_row(rb, w1); acc_row(rc, w2); acc_row(rd, w3);
    }
    for (; e < e1; e++) {
        int   c0 = g_col[e];
        float w0 = g_val[e];
        uint4 ra = __ldg((const uint4*)(xin + (size_t)c0 * FDIM + fo));
        acc_row(ra, w0);
    }

    if (beta != 0.f) {
        uint4 pr = __ldcs((const uint4*)(xprev + (size_t)r * FDIM + fo));
        float2 p0 = __half22float2(*reinterpret_cast<__half2*>(&pr.x));
        float2 p1 = __half22float2(*reinterpret_cast<__half2*>(&pr.y));
        float2 p2 = __half22float2(*reinterpret_cast<__half2*>(&pr.z));
        float2 p3 = __half22float2(*reinterpret_cast<__half2*>(&pr.w));
        s0 = alpha * s0 + beta * p0.x;  s1 = alpha * s1 + beta * p0.y;
        s2 = alpha * s2 + beta * p1.x;  s3 = alpha * s3 + beta * p1.y;
        s4 = alpha * s4 + beta * p2.x;  s5 = alpha * s5 + beta * p2.y;
        s6 = alpha * s6 + beta * p3.x;  s7 = alpha * s7 + beta * p3.y;
    } else {
        s0 *= alpha; s1 *= alpha; s2 *= alpha; s3 *= alpha;
        s4 *= alpha; s5 *= alpha; s6 *= alpha; s7 *= alpha;
    }
    __half2 o0 = __floats2half2_rn(s0, s1);
    __half2 o1 = __floats2half2_rn(s2, s3);
    __half2 o2 = __floats2half2_rn(s4, s5);
    __half2 o3 = __floats2half2_rn(s6, s7);
    uint4 st = make_uint4(*reinterpret_cast<uint32_t*>(&o0),
                          *reinterpret_cast<uint32_t*>(&o1),
                          *reinterpret_cast<uint32_t*>(&o2),
                          *reinterpret_cast<uint32_t*>(&o3));
    __stcs((uint4*)(xout + (size_t)r * FDIM + fo), st);
}

// ---------------- fp16 mma.sync GEMM (single W) --------------------------------
// Smem (dynamic, 32KB): A[2][512] uint4 (8KB each), B[2][512] uint4 (8KB each)
__global__ void __launch_bounds__(256, 2)
cheb_gemm_mma(const float* __restrict__ bias, float* __restrict__ out) {
    extern __shared__ uint4 sm4[];
    uint4* ASb = sm4;           // [2][512]
    uint4* BSb = sm4 + 1024;    // [2][512]

    int t     = threadIdx.x;
    int wid   = t >> 5;
    int lane  = t & 31;
    int mw    = wid & 3;
    int nw    = wid >> 2;
    int vbase = blockIdx.x * 128;
    int b     = blockIdx.y;

    float acc[2][8][4];
    #pragma unroll
    for (int i = 0; i < 2; i++)
        #pragma unroll
        for (int j = 0; j < 8; j++)
            #pragma unroll
            for (int q = 0; q < 4; q++) acc[i][j][q] = 0.f;

    // A staging mapping: thread (srow, par=ks)
    int par   = t & 1;
    int srow  = t >> 1;
    int smt   = srow >> 4;
    int rr    = srow & 15;
    int sg    = rr & 7;
    int shalf = rr >> 3;
    int v     = vbase + srow;
    bool vok  = (v < V);

    auto ldg_A = [&](uint4* areg, int ca) {
        int kb = ca >> 2;
        int cc = (ca & 3) * 32;
        const __half* arow = &g_x[kb][0] + (size_t)v * FDIM + b * CIN + cc + par * 16;
        if (vok) {
            areg[0] = *(const uint4*)(arow);
            areg[1] = *(const uint4*)(arow + 8);
        } else {
            areg[0] = make_uint4(0, 0, 0, 0);
            areg[1] = make_uint4(0, 0, 0, 0);
        }
    };
    auto sts_A = [&](uint4* areg, int bufi) {
        uint32_t* AS32 = reinterpret_cast<uint32_t*>(ASb + bufi * 512);
        uint32_t q0[4] = { areg[0].x, areg[0].y, areg[0].z, areg[0].w };
        uint32_t q1[4] = { areg[1].x, areg[1].y, areg[1].z, areg[1].w };
        #pragma unroll
        for (int i = 0; i < 4; i++) {
            int lane_i = sg * 4 + i;
            int word = ((smt * 2 + par) * 32 + lane_i) * 4 + 2 * shalf;
            *(uint2*)(AS32 + word) = make_uint2(q0[i], q1[i]);
        }
    };
    auto cp_B = [&](int ca, int bufi) {
        const uint4* src = reinterpret_cast<const uint4*>(g_wfrag[ca]);
        uint4* dst = BSb + bufi * 512;
        #pragma unroll
        for (int s = 0; s < 2; s++)
            cp_async16(dst + t + s * 256, src + t + s * 256);
        CP_COMMIT();
    };

    // ---- prologue
    uint4 areg[2], areg2[2];
    ldg_A(areg, 0);
    cp_B(0, 0);
    sts_A(areg, 0);
    ldg_A(areg2, 1);

    for (int ci = 0; ci < 16; ci++) {
        int cur = ci & 1;
        CP_WAIT0();
        __syncthreads();

        if (ci < 15) {
            cp_B(ci + 1, cur ^ 1);
            sts_A(areg2, cur ^ 1);
            if (ci < 14) ldg_A(areg, ci + 2);
            #pragma unroll
            for (int qi = 0; qi < 2; qi++) { uint4 tmp = areg[qi]; areg[qi] = areg2[qi]; areg2[qi] = tmp; }
        }

        uint4* AS4 = ASb + cur * 512;
        uint4* BS4 = BSb + cur * 512;

        uint4 au[2][2];
        #pragma unroll
        for (int mt2 = 0; mt2 < 2; mt2++) {
            int mt = mw * 2 + mt2;
            au[mt2][0] = AS4[(mt * 2 + 0) * 32 + lane];
            au[mt2][1] = AS4[(mt * 2 + 1) * 32 + lane];
        }
        #pragma unroll
        for (int nt8 = 0; nt8 < 8; nt8++) {
            int nt = nw * 8 + nt8;
            uint4 bu = BS4[nt * 32 + lane];   // {ks0b0, ks0b1, ks1b0, ks1b1}
            #pragma unroll
            for (int mt2 = 0; mt2 < 2; mt2++) {
                float* c = acc[mt2][nt8];
                mma_f16(c[0], c[1], c[2], c[3],
                        au[mt2][0].x, au[mt2][0].z, au[mt2][0].y, au[mt2][0].w,
                        bu.x, bu.y);
                mma_f16(c[0], c[1], c[2], c[3],
                        au[mt2][1].x, au[mt2][1].z, au[mt2][1].y, au[mt2][1].w,
                        bu.z, bu.w);
            }
        }
    }

    // ---- epilogue: streaming stores
    int gid  = lane >> 2;
    int tid4 = lane & 3;
    #pragma unroll
    for (int nt8 = 0; nt8 < 8; nt8++) {
        int o0 = nw * 64 + nt8 * 8 + tid4 * 2;
        float bi0 = __ldg(&bias[o0]);
        float bi1 = __ldg(&bias[o0 + 1]);
        #pragma unroll
        for (int mt2 = 0; mt2 < 2; mt2++) {
            int v0 = vbase + mw * 32 + mt2 * 16 + gid;
            const float* c = acc[mt2][nt8];
            if (v0 < V) {
                __stcs(&out[((size_t)b * COUT + o0)     * V + v0], c[0] + bi0);
                __stcs(&out[((size_t)b * COUT + o0 + 1) * V + v0], c[1] + bi1);
            }
            if (v0 + 8 < V) {
                __stcs(&out[((size_t)b * COUT + o0)     * V + v0 + 8], c[2] + bi0);
                __stcs(&out[((size_t)b * COUT + o0 + 1) * V + v0 + 8], c[3] + bi1);
            }
        }
    }
}

// ---------------- launcher ----------------------------------------------------
extern "C" void kernel_launch(void* const* d_in, const int* in_sizes, int n_in,
                              void* d_out, int out_size) {
    const float* x        = (const float*)d_in[0];
    const int*   edge_row = (const int*)d_in[1];
    const int*   edge_col = (const int*)d_in[2];
    const float* edge_val = (const float*)d_in[3];
    const float* weights  = (const float*)d_in[4];
    const float* biases   = (const float*)d_in[5];
    float*       out      = (float*)d_out;

    int E = in_sizes[1];

    static bool attr_set = false;
    if (!attr_set) {
        cudaFuncSetAttribute(cheb_gemm_mma,
                             cudaFuncAttributeMaxDynamicSharedMemorySize,
                             32768);
        attr_set = true;
    }

    int histBlocks  = (E + 255) / 256;
    int wprepBlocks = (KCHEB * COUT * 64 + 255) / 256;

    zero_hist_kernel<<<(VPAD + 255) / 256, 256>>>();
    prep1_kernel<<<TB_TOTAL + histBlocks, 256>>>(x, edge_row, E);
    scan_kernel<<<1, 1024>>>();
    prep2_kernel<<<histBlocks + wprepBlocks, 256>>>(edge_row, edge_col, edge_val, E,
                                                    weights, histBlocks);

    // Chebyshev recurrence
    {
        dim3 gb((V + 7) / 8, 2);
        spmm_cheb_kernel<<<gb, 256>>>(0, 0, 1, 1.f, 0.f);
        spmm_cheb_kernel<<<gb, 256>>>(1, 0, 2, 2.f, -1.f);
        spmm_cheb_kernel<<<gb, 256>>>(2, 1, 3, 2.f, -1.f);
    }

    // fp16 mma GEMM + bias + output permute
    {
        dim3 gb((V + 127) / 128, BDIM);
        cheb_gemm_mma<<<gb, 256, 32768>>>(biases, out);
    }
}